// round 10
// baseline (speedup 1.0000x reference)
#include <cuda_runtime.h>
#include <cuda_bf16.h>
#include <cstdint>

#define B_  128
#define L_  196
#define D_  1024
#define M_  (B_*L_)            // 25088

// ---------------- scratch (device globals; no allocation) ----------------
__device__ float g_c[B_*D_];          // c[b,e] = att_h + att_x + 3 biases
__device__ float g_scores[M_];        // pre-softmax scores
__device__ float g_part[7*B_*D_];     // L-split partial outputs
__device__ __nv_bfloat16 g_wa[D_*D_]; // W_a2a bf16
__device__ __nv_bfloat16 g_att[(size_t)M_*D_]; // att bf16 (51.4 MB)

// ---------------- helpers ----------------
static __device__ __forceinline__ float tanh_fast(float x){
    float y; asm("tanh.approx.f32 %0, %1;" : "=f"(y) : "f"(x)); return y;
}
static __device__ __forceinline__ unsigned smem_u32(const void* p){
    return (unsigned)__cvta_generic_to_shared(p);
}
static __device__ __forceinline__ void ldsm_x4(unsigned r[4], unsigned a){
    asm volatile("ldmatrix.sync.aligned.m8n8.x4.shared.b16 {%0,%1,%2,%3}, [%4];"
        : "=r"(r[0]),"=r"(r[1]),"=r"(r[2]),"=r"(r[3]) : "r"(a));
}
static __device__ __forceinline__ void mma16816(float d[4], const unsigned a[4],
                                                unsigned b0, unsigned b1){
    asm volatile("mma.sync.aligned.m16n8k16.row.col.f32.bf16.bf16.f32 "
        "{%0,%1,%2,%3}, {%4,%5,%6,%7}, {%8,%9}, {%0,%1,%2,%3};"
        : "+f"(d[0]),"+f"(d[1]),"+f"(d[2]),"+f"(d[3])
        : "r"(a[0]),"r"(a[1]),"r"(a[2]),"r"(a[3]),"r"(b0),"r"(b1));
}
static __device__ __forceinline__ void cp16(unsigned dst, const void* src){
    asm volatile("cp.async.cg.shared.global [%0], [%1], 16;" :: "r"(dst), "l"(src));
}
static __device__ __forceinline__ void cp_commit(){ asm volatile("cp.async.commit_group;"); }
static __device__ __forceinline__ void cp_wait0(){
    asm volatile("cp.async.wait_group 0;" ::: "memory");
}

// ---------------- kernel 0: merged prologue ----------------
// blocks [0,1024): W_a2a fp32->bf16 ; [1024,26112): att fp32->bf16 ;
// [26112,26368): c[b,e] = h@Wh^T + x@Wx^T + (bh+bx+ba)
__global__ __launch_bounds__(256) void k_prep(
        const float* __restrict__ W, const float* __restrict__ A,
        const float* __restrict__ h, const float* __restrict__ x,
        const float* __restrict__ Wh, const float* __restrict__ Wx,
        const float* __restrict__ bh, const float* __restrict__ bx,
        const float* __restrict__ ba){
    __shared__ float hs[4][1024];
    __shared__ float xs[4][1024];
    const int bid = blockIdx.x, tid = threadIdx.x;
    if (bid < 1024){
        int i = (bid*256 + tid)*4;
        float4 v = *reinterpret_cast<const float4*>(W + i);
        *reinterpret_cast<__nv_bfloat162*>(&g_wa[i  ]) = __floats2bfloat162_rn(v.x, v.y);
        *reinterpret_cast<__nv_bfloat162*>(&g_wa[i+2]) = __floats2bfloat162_rn(v.z, v.w);
        return;
    }
    if (bid < 1024 + 25088){
        size_t i = ((size_t)(bid-1024)*256 + tid)*4;
        float4 v = *reinterpret_cast<const float4*>(A + i);
        *reinterpret_cast<__nv_bfloat162*>(&g_att[i  ]) = __floats2bfloat162_rn(v.x, v.y);
        *reinterpret_cast<__nv_bfloat162*>(&g_att[i+2]) = __floats2bfloat162_rn(v.z, v.w);
        return;
    }
    // ---- cvec part ----
    const int idx = bid - 26112;            // 0..255
    const int gx = idx & 31, gy = idx >> 5; // 32 x 8
    const int wid = tid>>5, lane = tid&31;
    const int b0 = gx*4;
    for (int i = tid; i < 1024; i += 256){
        int row = i >> 8, c = (i & 255) << 2;
        *reinterpret_cast<float4*>(&hs[row][c]) =
            *reinterpret_cast<const float4*>(h + (size_t)(b0+row)*1024 + c);
        *reinterpret_cast<float4*>(&xs[row][c]) =
            *reinterpret_cast<const float4*>(x + (size_t)(b0+row)*1024 + c);
    }
    __syncthreads();
    const int ebase = gy*128 + wid*16;
    for (int eo = 0; eo < 16; eo += 2){
        float acc[2][4] = {{0.f,0.f,0.f,0.f},{0.f,0.f,0.f,0.f}};
        const int e0 = ebase + eo;
        const float4* wh0 = reinterpret_cast<const float4*>(Wh + (size_t)e0*1024);
        const float4* wx0 = reinterpret_cast<const float4*>(Wx + (size_t)e0*1024);
        const float4* wh1 = reinterpret_cast<const float4*>(Wh + (size_t)(e0+1)*1024);
        const float4* wx1 = reinterpret_cast<const float4*>(Wx + (size_t)(e0+1)*1024);
        #pragma unroll
        for (int it = 0; it < 8; ++it){
            const int d4 = it*32 + lane;
            float4 wv0 = wh0[d4], xv0 = wx0[d4], wv1 = wh1[d4], xv1 = wx1[d4];
            #pragma unroll
            for (int b = 0; b < 4; ++b){
                float4 hv = *reinterpret_cast<const float4*>(&hs[b][d4<<2]);
                float4 gv = *reinterpret_cast<const float4*>(&xs[b][d4<<2]);
                acc[0][b] += wv0.x*hv.x + wv0.y*hv.y + wv0.z*hv.z + wv0.w*hv.w
                           + xv0.x*gv.x + xv0.y*gv.y + xv0.z*gv.z + xv0.w*gv.w;
                acc[1][b] += wv1.x*hv.x + wv1.y*hv.y + wv1.z*hv.z + wv1.w*hv.w
                           + xv1.x*gv.x + xv1.y*gv.y + xv1.z*gv.z + xv1.w*gv.w;
            }
        }
        #pragma unroll
        for (int u = 0; u < 2; ++u){
            #pragma unroll
            for (int b = 0; b < 4; ++b){
                float v = acc[u][b];
                v += __shfl_xor_sync(0xffffffffu, v, 16);
                v += __shfl_xor_sync(0xffffffffu, v, 8);
                v += __shfl_xor_sync(0xffffffffu, v, 4);
                v += __shfl_xor_sync(0xffffffffu, v, 2);
                v += __shfl_xor_sync(0xffffffffu, v, 1);
                acc[u][b] = v;
            }
            if (lane < 4){
                const int e = e0 + u;
                g_c[(size_t)(b0+lane)*1024 + e] = acc[u][lane] + bh[e] + bx[e] + ba[e];
            }
        }
    }
}

// ---------------- kernel 1: fused GEMM + tanh + dot(W_d2d) -> scores ----------------
// 256 threads, 2 CTAs/SM. CTA = 64 att rows, streamed A+B, double-buffered,
// XOR-swizzled. 4 n-chunks x 16 k-chunks (k=64). Warp tile 32m x 64n.
// B fragments via ldsm_x4 (n16 x k16 per instruction).
#define ABUF    8192               // 64 rows * 128B
#define B_OFF   16384
#define BBUF    32768              // 256 rows * 128B
#define CS_OFF  81920
#define WD_OFF  90112
#define SSC_OFF 94208
#define SM_SZ   94464

__global__ void __launch_bounds__(256, 2) k_scores(const float* __restrict__ wdd){
    extern __shared__ char sm[];
    const int tid = threadIdx.x, lane = tid & 31, wid = tid >> 5;
    const int m0 = blockIdx.x * 64;
    const int b0 = m0 / L_;
    const unsigned smb = smem_u32(sm);
    float* cs  = reinterpret_cast<float*>(sm + CS_OFF);
    float* wds = reinterpret_cast<float*>(sm + WD_OFF);
    float* ssc = reinterpret_cast<float*>(sm + SSC_OFF);

    // ---- constants ----
    {
        int b1 = (m0 + 63) / L_; if (b1 > B_-1) b1 = B_-1;
        for (int i = tid; i < 2048; i += 256){
            int w = i >> 10, e = i & 1023;
            cs[i] = g_c[(size_t)(w ? b1 : b0)*1024 + e];
        }
        for (int i = tid; i < 1024; i += 256) wds[i] = wdd[i];
        if (tid < 64) ssc[tid] = 0.f;
    }

    const int m_off = (wid >> 2) * 32;        // 0,32
    const int n_off = (wid & 3) * 64;         // 0..192 within 256-wide n-chunk
    const unsigned v  = (unsigned)(lane & 7); // swizzle key
    const unsigned ua = (unsigned)(lane >> 4);
    const unsigned ub = (unsigned)((lane >> 3) & 1);
    const unsigned a_row = smb + (unsigned)((m_off + (lane & 15)) * 128);
    unsigned b_row4[4];
    #pragma unroll
    for (int p = 0; p < 4; ++p)
        b_row4[p] = smb + B_OFF + (unsigned)((n_off + p*16 + (lane & 7)
                  + ((lane >> 4) << 3)) * 128);

    const float* crow[2][2]; int rowl[2][2];
    #pragma unroll
    for (int mt = 0; mt < 2; ++mt)
        #pragma unroll
        for (int hf = 0; hf < 2; ++hf){
            const int r = m_off + mt*16 + (lane >> 2) + hf*8;
            rowl[mt][hf] = r;
            crow[mt][hf] = cs + (((m0 + r)/L_ != b0) ? 1024 : 0);
        }

    // ---- precomputed loader addressing (per thread: 2 A + 8 B granules) ----
    const int lr = tid >> 3, lc = tid & 7;
    const __nv_bfloat16* pA = g_att + ((size_t)(m0 + lr) << 10) + lc*8;
    const __nv_bfloat16* pB = g_wa + ((size_t)lr << 10) + lc*8;
    const unsigned dsw = (unsigned)(((lc ^ (lr & 7)) << 4) + lr*128);
    const unsigned dA = smb + dsw;
    const unsigned dB = smb + B_OFF + dsw;

    auto load_step = [&](int t, int buf){
        const unsigned offA = (unsigned)((t & 15) << 6);
        const unsigned off  = (unsigned)((t >> 4) << 18) + offA;
        const unsigned ba_ = (unsigned)(buf*ABUF), bb_ = (unsigned)(buf*BBUF);
        cp16(dA + ba_,            pA + offA);
        cp16(dA + ba_ + 32*128,   pA + offA + 32*1024);
        #pragma unroll
        for (int j = 0; j < 8; ++j)
            cp16(dB + bb_ + (unsigned)(j*32*128), pB + off + j*32*1024);
    };

    float acc[2][8][4];
    load_step(0, 0);
    cp_commit();

    for (int nc = 0; nc < 4; ++nc){
        #pragma unroll
        for (int mt = 0; mt < 2; ++mt)
            #pragma unroll
            for (int nt = 0; nt < 8; ++nt)
                #pragma unroll
                for (int i = 0; i < 4; ++i) acc[mt][nt][i] = 0.f;

        for (int kc = 0; kc < 16; ++kc){
            const int s = nc*16 + kc;
            cp_wait0();
            __syncthreads();
            if (s < 63){ load_step(s+1, (s+1)&1); cp_commit(); }

            const unsigned ao = (unsigned)((s & 1) * ABUF);
            const unsigned bo = (unsigned)((s & 1) * BBUF);
            #pragma unroll
            for (int ks = 0; ks < 4; ++ks){
                unsigned af[2][4], bf[4][4];
                const unsigned ca = (((unsigned)(2*ks) + ua) ^ v) << 4;
                #pragma unroll
                for (int mt = 0; mt < 2; ++mt)
                    ldsm_x4(af[mt], a_row + ao + (unsigned)(mt*2048) + ca);
                const unsigned cb = (((unsigned)(2*ks) + ub) ^ v) << 4;
                #pragma unroll
                for (int p = 0; p < 4; ++p)
                    ldsm_x4(bf[p], b_row4[p] + bo + cb);
                #pragma unroll
                for (int mt = 0; mt < 2; ++mt)
                    #pragma unroll
                    for (int p = 0; p < 4; ++p){
                        mma16816(acc[mt][2*p  ], af[mt], bf[p][0], bf[p][1]);
                        mma16816(acc[mt][2*p+1], af[mt], bf[p][2], bf[p][3]);
                    }
            }
        }

        // fused epilogue: tanh(acc + c) * W_d2d, reduce, accumulate per row
        const int n0c = nc * 256;
        #pragma unroll
        for (int mt = 0; mt < 2; ++mt)
            #pragma unroll
            for (int hf = 0; hf < 2; ++hf){
                float vsum = 0.f;
                const float* cr = crow[mt][hf];
                #pragma unroll
                for (int nt = 0; nt < 8; ++nt){
                    const int e0 = n0c + n_off + nt*8 + (lane & 3)*2;
                    vsum += tanh_fast(acc[mt][nt][hf*2+0] + cr[e0  ]) * wds[e0  ];
                    vsum += tanh_fast(acc[mt][nt][hf*2+1] + cr[e0+1]) * wds[e0+1];
                }
                vsum += __shfl_xor_sync(0xffffffffu, vsum, 1);
                vsum += __shfl_xor_sync(0xffffffffu, vsum, 2);
                if ((lane & 3) == 0) atomicAdd(&ssc[rowl[mt][hf]], vsum);
            }
    }
    __syncthreads();
    if (tid < 64) g_scores[m0 + tid] = ssc[tid];   // b_d2d dropped (softmax shift-invariant)
}

// ---------------- kernel 2: softmax + L-split(7) weighted partial sums ----------------
__global__ __launch_bounds__(256) void k_outp(const float* __restrict__ att){
    __shared__ float sc[256];
    __shared__ float red[256];
    const int b = blockIdx.x, q = blockIdx.y, tid = threadIdx.x;
    const float s = (tid < L_) ? g_scores[b*L_ + tid] : -1e30f;
    red[tid] = s; __syncthreads();
    #pragma unroll
    for (int o = 128; o > 0; o >>= 1){
        if (tid < o) red[tid] = fmaxf(red[tid], red[tid+o]);
        __syncthreads();
    }
    const float mx = red[0]; __syncthreads();
    const float e = (tid < L_) ? __expf(s - mx) : 0.f;
    sc[tid] = e; red[tid] = e; __syncthreads();
    #pragma unroll
    for (int o = 128; o > 0; o >>= 1){
        if (tid < o) red[tid] += red[tid+o];
        __syncthreads();
    }
    const float inv = 1.f / red[0];
    __syncthreads();

    const float4* ap = reinterpret_cast<const float4*>(att)
                     + (size_t)b*L_*256 + (size_t)q*28*256 + tid;
    float4 acc = make_float4(0.f,0.f,0.f,0.f);
    #pragma unroll 7
    for (int l = 0; l < 28; ++l){
        float4 vv = ap[(size_t)l*256];
        const float wl = sc[q*28 + l] * inv;
        acc.x += wl*vv.x; acc.y += wl*vv.y; acc.z += wl*vv.z; acc.w += wl*vv.w;
    }
    reinterpret_cast<float4*>(g_part)[((size_t)q*B_ + b)*256 + tid] = acc;
}

// ---------------- kernel 3: combine 7 partials ----------------
__global__ __launch_bounds__(256) void k_out2(float* __restrict__ out){
    const int b = blockIdx.x, tid = threadIdx.x;
    const float4* p = reinterpret_cast<const float4*>(g_part);
    float4 r = make_float4(0.f,0.f,0.f,0.f);
    #pragma unroll
    for (int q = 0; q < 7; ++q){
        float4 a = p[((size_t)q*B_ + b)*256 + tid];
        r.x += a.x; r.y += a.y; r.z += a.z; r.w += a.w;
    }
    reinterpret_cast<float4*>(out)[(size_t)b*256 + tid] = r;
}

// ---------------- launch ----------------
extern "C" void kernel_launch(void* const* d_in, const int* in_sizes, int n_in,
                              void* d_out, int out_size) {
    const float* x   = (const float*)d_in[0];
    const float* att = (const float*)d_in[1];
    const float* h   = (const float*)d_in[2];
    const float* Wa  = (const float*)d_in[3];
    const float* ba  = (const float*)d_in[4];
    const float* Wh  = (const float*)d_in[5];
    const float* bh  = (const float*)d_in[6];
    const float* Wx  = (const float*)d_in[7];
    const float* bx  = (const float*)d_in[8];
    const float* wd  = (const float*)d_in[9];
    float* out = (float*)d_out;

    cudaFuncSetAttribute(k_scores, cudaFuncAttributeMaxDynamicSharedMemorySize, SM_SZ);

    k_prep<<<1024 + 25088 + 256, 256>>>(Wa, att, h, x, Wh, Wx, bh, bx, ba);
    k_scores<<<M_/64, 256, SM_SZ>>>(wd);
    k_outp<<<dim3(B_, 7), 256>>>(att);
    k_out2<<<B_, 256>>>(out);
}

// round 11
// speedup vs baseline: 1.3874x; 1.3874x over previous
#include <cuda_runtime.h>
#include <cuda_bf16.h>
#include <cstdint>

#define B_  128
#define L_  196
#define D_  1024
#define M_  (B_*L_)            // 25088

// ---------------- scratch (device globals; no allocation) ----------------
__device__ float g_c[B_*D_];          // c[b,e] = att_h + att_x + 3 biases
__device__ float g_scores[M_];        // pre-softmax scores
__device__ float g_part[7*B_*D_];     // L-split partial outputs
__device__ __nv_bfloat16 g_wa[D_*D_]; // W_a2a bf16
__device__ __nv_bfloat16 g_att[(size_t)M_*D_]; // att bf16 (51.4 MB)

// ---------------- helpers ----------------
static __device__ __forceinline__ float tanh_fast(float x){
    float y; asm("tanh.approx.f32 %0, %1;" : "=f"(y) : "f"(x)); return y;
}
static __device__ __forceinline__ unsigned smem_u32(const void* p){
    return (unsigned)__cvta_generic_to_shared(p);
}
static __device__ __forceinline__ void ldsm_x4(unsigned r[4], unsigned a){
    asm volatile("ldmatrix.sync.aligned.m8n8.x4.shared.b16 {%0,%1,%2,%3}, [%4];"
        : "=r"(r[0]),"=r"(r[1]),"=r"(r[2]),"=r"(r[3]) : "r"(a));
}
static __device__ __forceinline__ void ldsm_x2(unsigned r[2], unsigned a){
    asm volatile("ldmatrix.sync.aligned.m8n8.x2.shared.b16 {%0,%1}, [%2];"
        : "=r"(r[0]),"=r"(r[1]) : "r"(a));
}
static __device__ __forceinline__ void mma16816(float d[4], const unsigned a[4], const unsigned b[2]){
    asm volatile("mma.sync.aligned.m16n8k16.row.col.f32.bf16.bf16.f32 "
        "{%0,%1,%2,%3}, {%4,%5,%6,%7}, {%8,%9}, {%0,%1,%2,%3};"
        : "+f"(d[0]),"+f"(d[1]),"+f"(d[2]),"+f"(d[3])
        : "r"(a[0]),"r"(a[1]),"r"(a[2]),"r"(a[3]),"r"(b[0]),"r"(b[1]));
}
static __device__ __forceinline__ void cp16(unsigned dst, const void* src){
    asm volatile("cp.async.cg.shared.global [%0], [%1], 16;" :: "r"(dst), "l"(src));
}
static __device__ __forceinline__ void cp_commit(){ asm volatile("cp.async.commit_group;"); }
static __device__ __forceinline__ void cp_wait0(){
    asm volatile("cp.async.wait_group 0;" ::: "memory");
}

// ---------------- kernel 0a: W_a2a fp32 -> bf16 ----------------
__global__ __launch_bounds__(256) void k_convert_w(const float* __restrict__ W){
    int i = (blockIdx.x*256 + threadIdx.x)*4;
    float4 v = *reinterpret_cast<const float4*>(W + i);
    *reinterpret_cast<__nv_bfloat162*>(&g_wa[i  ]) = __floats2bfloat162_rn(v.x, v.y);
    *reinterpret_cast<__nv_bfloat162*>(&g_wa[i+2]) = __floats2bfloat162_rn(v.z, v.w);
}
// ---------------- kernel 0b: att fp32 -> bf16 ----------------
__global__ __launch_bounds__(256) void k_convert_att(const float* __restrict__ A){
    size_t i = ((size_t)blockIdx.x*256 + threadIdx.x)*4;
    float4 v = *reinterpret_cast<const float4*>(A + i);
    *reinterpret_cast<__nv_bfloat162*>(&g_att[i  ]) = __floats2bfloat162_rn(v.x, v.y);
    *reinterpret_cast<__nv_bfloat162*>(&g_att[i+2]) = __floats2bfloat162_rn(v.z, v.w);
}

// ---------------- kernel 1: c[b,e] = h@Wh^T + x@Wx^T + (bh+bx+ba) ----------------
// Block = 16 b x 32 e (grid 8 x 32). h/x tiles in 128 KB dynamic smem.
// Warp = 4 e x 16 b fp32 accumulators, lane-sliced K (32 floats per lane).
__global__ __launch_bounds__(256) void k_cvec2(
        const float* __restrict__ h, const float* __restrict__ x,
        const float* __restrict__ Wh, const float* __restrict__ Wx,
        const float* __restrict__ bh, const float* __restrict__ bx,
        const float* __restrict__ ba){
    extern __shared__ float sh[];          // hs[16*1024] xs[16*1024]
    float* hs = sh;
    float* xs = sh + 16*1024;
    const int tid = threadIdx.x, wid = tid>>5, lane = tid&31;
    const int b0 = blockIdx.x * 16;
    const int e0 = blockIdx.y * 32 + wid * 4;

    for (int i = tid; i < 4096; i += 256){ // 16 rows x 256 float4 (x2 arrays)
        int row = i >> 8, c = (i & 255) << 2;
        *reinterpret_cast<float4*>(&hs[row*1024 + c]) =
            *reinterpret_cast<const float4*>(h + (size_t)(b0+row)*1024 + c);
        *reinterpret_cast<float4*>(&xs[row*1024 + c]) =
            *reinterpret_cast<const float4*>(x + (size_t)(b0+row)*1024 + c);
    }
    __syncthreads();

    float acc[4][16];
    #pragma unroll
    for (int e = 0; e < 4; ++e)
        #pragma unroll
        for (int b = 0; b < 16; ++b) acc[e][b] = 0.f;

    const float4* wh4[4]; const float4* wx4[4];
    #pragma unroll
    for (int e = 0; e < 4; ++e){
        wh4[e] = reinterpret_cast<const float4*>(Wh + (size_t)(e0+e)*1024);
        wx4[e] = reinterpret_cast<const float4*>(Wx + (size_t)(e0+e)*1024);
    }

    #pragma unroll
    for (int k = 0; k < 8; ++k){
        const int d4 = lane*8 + k;         // float4 index into K
        float4 wv[4], xv[4];
        #pragma unroll
        for (int e = 0; e < 4; ++e){ wv[e] = wh4[e][d4]; xv[e] = wx4[e][d4]; }
        #pragma unroll
        for (int b = 0; b < 16; ++b){
            float4 hv = *reinterpret_cast<const float4*>(&hs[b*1024 + (d4<<2)]);
            float4 gv = *reinterpret_cast<const float4*>(&xs[b*1024 + (d4<<2)]);
            #pragma unroll
            for (int e = 0; e < 4; ++e){
                acc[e][b] += wv[e].x*hv.x + wv[e].y*hv.y + wv[e].z*hv.z + wv[e].w*hv.w;
                acc[e][b] += xv[e].x*gv.x + xv[e].y*gv.y + xv[e].z*gv.z + xv[e].w*gv.w;
            }
        }
    }

    // butterfly-reduce every accumulator across the warp (all lanes get totals)
    #pragma unroll
    for (int e = 0; e < 4; ++e)
        #pragma unroll
        for (int b = 0; b < 16; ++b){
            float v = acc[e][b];
            v += __shfl_xor_sync(0xffffffffu, v, 16);
            v += __shfl_xor_sync(0xffffffffu, v, 8);
            v += __shfl_xor_sync(0xffffffffu, v, 4);
            v += __shfl_xor_sync(0xffffffffu, v, 2);
            v += __shfl_xor_sync(0xffffffffu, v, 1);
            acc[e][b] = v;
        }
    #pragma unroll
    for (int t = 0; t < 2; ++t){
        const int idx = lane + t*32;       // 0..63 -> (e, b)
        const int e = idx >> 4, b = idx & 15;
        const int eg = e0 + e;
        g_c[(size_t)(b0+b)*1024 + eg] = acc[e][b] + bh[eg] + bx[eg] + ba[eg];
    }
}

// ---------------- kernel 2: fused GEMM + tanh + dot(W_d2d) -> scores ----------------
// (exact R9 version, measured 178us) 256 threads, 2 CTAs/SM. CTA = 64 att rows.
// A+B streamed, double-buffered, XOR-swizzled. 64 flat steps. Warp tile 32m x 64n.
#define ABUF    8192               // 64 rows * 128B
#define B_OFF   16384
#define BBUF    32768              // 256 rows * 128B
#define CS_OFF  81920
#define WD_OFF  90112
#define SSC_OFF 94208
#define SM_SZ   94464

__global__ void __launch_bounds__(256, 2) k_scores(const float* __restrict__ wdd){
    extern __shared__ char sm[];
    const int tid = threadIdx.x, lane = tid & 31, wid = tid >> 5;
    const int m0 = blockIdx.x * 64;
    const int b0 = m0 / L_;
    const unsigned smb = smem_u32(sm);
    float* cs  = reinterpret_cast<float*>(sm + CS_OFF);
    float* wds = reinterpret_cast<float*>(sm + WD_OFF);
    float* ssc = reinterpret_cast<float*>(sm + SSC_OFF);

    // ---- constants ----
    {
        int b1 = (m0 + 63) / L_; if (b1 > B_-1) b1 = B_-1;
        for (int i = tid; i < 2048; i += 256){
            int w = i >> 10, e = i & 1023;
            cs[i] = g_c[(size_t)(w ? b1 : b0)*1024 + e];
        }
        for (int i = tid; i < 1024; i += 256) wds[i] = wdd[i];
        if (tid < 64) ssc[tid] = 0.f;
    }

    const int m_off = (wid >> 2) * 32;        // 0,32
    const int n_off = (wid & 3) * 64;         // 0..192 within 256-wide n-chunk
    const unsigned v  = (unsigned)(lane & 7); // swizzle key (row&7 for both operands)
    const unsigned ua = (unsigned)(lane >> 4);
    const unsigned ub = (unsigned)((lane >> 3) & 1);
    const unsigned a_row = smb + (unsigned)((m_off + (lane & 15)) * 128);
    const unsigned b_row = smb + B_OFF + (unsigned)((n_off + (lane & 7)) * 128);

    const float* crow[2][2]; int rowl[2][2];
    #pragma unroll
    for (int mt = 0; mt < 2; ++mt)
        #pragma unroll
        for (int hf = 0; hf < 2; ++hf){
            const int r = m_off + mt*16 + (lane >> 2) + hf*8;
            rowl[mt][hf] = r;
            crow[mt][hf] = cs + (((m0 + r)/L_ != b0) ? 1024 : 0);
        }

    // tile loader: step t -> n0=(t>>4)*256, kk=(t&15)*64; XOR-swizzled stores
    auto load_step = [&](int t, int buf){
        const int n0 = (t >> 4) * 256, kk = (t & 15) * 64;
        #pragma unroll
        for (int i = 0; i < 2; ++i){             // A: 64x64 bf16 = 512 granules
            const int idx = tid + i*256;
            const int r = idx >> 3, c = idx & 7;
            cp16(smb + (unsigned)(buf*ABUF + r*128 + (((unsigned)c ^ (r&7))<<4)),
                 g_att + ((size_t)(m0 + r) << 10) + kk + c*8);
        }
        #pragma unroll
        for (int i = 0; i < 8; ++i){             // B: 256x64 bf16 = 2048 granules
            const int idx = tid + i*256;
            const int r = idx >> 3, c = idx & 7;
            cp16(smb + B_OFF + (unsigned)(buf*BBUF + r*128 + (((unsigned)c ^ (r&7))<<4)),
                 g_wa + ((size_t)(n0 + r) << 10) + kk + c*8);
        }
    };

    float acc[2][8][4];
    load_step(0, 0);
    cp_commit();

    for (int s = 0; s < 64; ++s){
        const int kc = s & 15;
        cp_wait0();                  // step-s tiles arrived
        __syncthreads();             // all warps done reading buffer (s+1)&1
        if (s < 63){ load_step(s+1, (s+1)&1); cp_commit(); }

        if (kc == 0){
            #pragma unroll
            for (int mt = 0; mt < 2; ++mt)
                #pragma unroll
                for (int nt = 0; nt < 8; ++nt)
                    #pragma unroll
                    for (int i = 0; i < 4; ++i) acc[mt][nt][i] = 0.f;
        }
        const unsigned ao = (unsigned)((s & 1) * ABUF);
        const unsigned bo = (unsigned)((s & 1) * BBUF);
        #pragma unroll
        for (int ks = 0; ks < 4; ++ks){
            unsigned af[2][4], bf[8][2];
            const unsigned ca = (((unsigned)(2*ks) + ua) ^ v) << 4;
            #pragma unroll
            for (int mt = 0; mt < 2; ++mt)
                ldsm_x4(af[mt], a_row + ao + (unsigned)(mt*2048) + ca);
            const unsigned cb = (((unsigned)(2*ks) + ub) ^ v) << 4;
            #pragma unroll
            for (int nt = 0; nt < 8; ++nt)
                ldsm_x2(bf[nt], b_row + bo + (unsigned)(nt*1024) + cb);
            #pragma unroll
            for (int mt = 0; mt < 2; ++mt)
                #pragma unroll
                for (int nt = 0; nt < 8; ++nt)
                    mma16816(acc[mt][nt], af[mt], bf[nt]);
        }

        if (kc == 15){   // n-chunk complete: fused tanh*W_d2d epilogue
            const int n0c = (s >> 4) * 256;
            #pragma unroll
            for (int mt = 0; mt < 2; ++mt)
                #pragma unroll
                for (int hf = 0; hf < 2; ++hf){
                    float vsum = 0.f;
                    const float* cr = crow[mt][hf];
                    #pragma unroll
                    for (int nt = 0; nt < 8; ++nt){
                        const int e0 = n0c + n_off + nt*8 + (lane & 3)*2;
                        vsum += tanh_fast(acc[mt][nt][hf*2+0] + cr[e0  ]) * wds[e0  ];
                        vsum += tanh_fast(acc[mt][nt][hf*2+1] + cr[e0+1]) * wds[e0+1];
                    }
                    vsum += __shfl_xor_sync(0xffffffffu, vsum, 1);
                    vsum += __shfl_xor_sync(0xffffffffu, vsum, 2);
                    if ((lane & 3) == 0) atomicAdd(&ssc[rowl[mt][hf]], vsum);
                }
        }
    }
    __syncthreads();
    if (tid < 64) g_scores[m0 + tid] = ssc[tid];   // b_d2d dropped (softmax shift-invariant)
}

// ---------------- kernel 3a: softmax + L-split(7) weighted partial sums ----------------
__global__ __launch_bounds__(256) void k_outp(const float* __restrict__ att){
    __shared__ float sc[256];
    __shared__ float red[256];
    const int b = blockIdx.x, q = blockIdx.y, tid = threadIdx.x;
    const float s = (tid < L_) ? g_scores[b*L_ + tid] : -1e30f;
    red[tid] = s; __syncthreads();
    #pragma unroll
    for (int o = 128; o > 0; o >>= 1){
        if (tid < o) red[tid] = fmaxf(red[tid], red[tid+o]);
        __syncthreads();
    }
    const float mx = red[0]; __syncthreads();
    const float e = (tid < L_) ? __expf(s - mx) : 0.f;
    sc[tid] = e; red[tid] = e; __syncthreads();
    #pragma unroll
    for (int o = 128; o > 0; o >>= 1){
        if (tid < o) red[tid] += red[tid+o];
        __syncthreads();
    }
    const float inv = 1.f / red[0];
    __syncthreads();

    const float4* ap = reinterpret_cast<const float4*>(att)
                     + (size_t)b*L_*256 + (size_t)q*28*256 + tid;
    float4 acc = make_float4(0.f,0.f,0.f,0.f);
    #pragma unroll 7
    for (int l = 0; l < 28; ++l){
        float4 vv = ap[(size_t)l*256];
        const float wl = sc[q*28 + l] * inv;
        acc.x += wl*vv.x; acc.y += wl*vv.y; acc.z += wl*vv.z; acc.w += wl*vv.w;
    }
    reinterpret_cast<float4*>(g_part)[((size_t)q*B_ + b)*256 + tid] = acc;
}

// ---------------- kernel 3b: combine 7 partials ----------------
__global__ __launch_bounds__(256) void k_out2(float* __restrict__ out){
    const int b = blockIdx.x, tid = threadIdx.x;
    const float4* p = reinterpret_cast<const float4*>(g_part);
    float4 r = make_float4(0.f,0.f,0.f,0.f);
    #pragma unroll
    for (int q = 0; q < 7; ++q){
        float4 a = p[((size_t)q*B_ + b)*256 + tid];
        r.x += a.x; r.y += a.y; r.z += a.z; r.w += a.w;
    }
    reinterpret_cast<float4*>(out)[(size_t)b*256 + tid] = r;
}

// ---------------- launch ----------------
extern "C" void kernel_launch(void* const* d_in, const int* in_sizes, int n_in,
                              void* d_out, int out_size) {
    const float* x   = (const float*)d_in[0];
    const float* att = (const float*)d_in[1];
    const float* h   = (const float*)d_in[2];
    const float* Wa  = (const float*)d_in[3];
    const float* ba  = (const float*)d_in[4];
    const float* Wh  = (const float*)d_in[5];
    const float* bh  = (const float*)d_in[6];
    const float* Wx  = (const float*)d_in[7];
    const float* bx  = (const float*)d_in[8];
    const float* wd  = (const float*)d_in[9];
    float* out = (float*)d_out;

    cudaFuncSetAttribute(k_scores, cudaFuncAttributeMaxDynamicSharedMemorySize, SM_SZ);
    cudaFuncSetAttribute(k_cvec2, cudaFuncAttributeMaxDynamicSharedMemorySize, 131072);

    k_convert_w<<<1024, 256>>>(Wa);
    k_convert_att<<<(int)(((size_t)M_*D_)/1024), 256>>>(att);
    k_cvec2<<<dim3(8, 32), 256, 131072>>>(h, x, Wh, Wx, bh, bx, ba);
    k_scores<<<M_/64, 256, SM_SZ>>>(wd);
    k_outp<<<dim3(B_, 7), 256>>>(att);
    k_out2<<<B_, 256>>>(out);
}

// round 12
// speedup vs baseline: 1.4008x; 1.0097x over previous
#include <cuda_runtime.h>
#include <cuda_bf16.h>
#include <cstdint>

#define B_  128
#define L_  196
#define D_  1024
#define M_  (B_*L_)            // 25088

// ---------------- scratch (device globals; no allocation) ----------------
__device__ float g_c[B_*D_];          // c[b,e] = att_h + att_x + 3 biases
__device__ float g_scores[M_];        // pre-softmax scores
__device__ float g_part[7*B_*D_];     // L-split partial outputs
__device__ __nv_bfloat16 g_wa[D_*D_]; // W_a2a bf16
__device__ __nv_bfloat16 g_att[(size_t)M_*D_]; // att bf16 (51.4 MB)

// ---------------- helpers ----------------
static __device__ __forceinline__ float tanh_fast(float x){
    float y; asm("tanh.approx.f32 %0, %1;" : "=f"(y) : "f"(x)); return y;
}
static __device__ __forceinline__ unsigned smem_u32(const void* p){
    return (unsigned)__cvta_generic_to_shared(p);
}
static __device__ __forceinline__ void ldsm_x4(unsigned r[4], unsigned a){
    asm volatile("ldmatrix.sync.aligned.m8n8.x4.shared.b16 {%0,%1,%2,%3}, [%4];"
        : "=r"(r[0]),"=r"(r[1]),"=r"(r[2]),"=r"(r[3]) : "r"(a));
}
static __device__ __forceinline__ void mma16816(float d[4], const unsigned a[4],
                                                unsigned b0, unsigned b1){
    asm volatile("mma.sync.aligned.m16n8k16.row.col.f32.bf16.bf16.f32 "
        "{%0,%1,%2,%3}, {%4,%5,%6,%7}, {%8,%9}, {%0,%1,%2,%3};"
        : "+f"(d[0]),"+f"(d[1]),"+f"(d[2]),"+f"(d[3])
        : "r"(a[0]),"r"(a[1]),"r"(a[2]),"r"(a[3]),"r"(b0),"r"(b1));
}
static __device__ __forceinline__ void cp16(unsigned dst, const void* src){
    asm volatile("cp.async.cg.shared.global [%0], [%1], 16;" :: "r"(dst), "l"(src));
}
static __device__ __forceinline__ void cp_commit(){ asm volatile("cp.async.commit_group;"); }
static __device__ __forceinline__ void cp_wait0(){
    asm volatile("cp.async.wait_group 0;" ::: "memory");
}

// ---------------- kernel 0: merged fp32->bf16 converts (W then att) ----------------
__global__ __launch_bounds__(256) void k_convert(const float* __restrict__ W,
                                                 const float* __restrict__ A){
    const int bid = blockIdx.x;
    if (bid < 1024){
        int i = (bid*256 + threadIdx.x)*4;
        float4 v = *reinterpret_cast<const float4*>(W + i);
        *reinterpret_cast<__nv_bfloat162*>(&g_wa[i  ]) = __floats2bfloat162_rn(v.x, v.y);
        *reinterpret_cast<__nv_bfloat162*>(&g_wa[i+2]) = __floats2bfloat162_rn(v.z, v.w);
    } else {
        size_t i = ((size_t)(bid-1024)*256 + threadIdx.x)*4;
        float4 v = *reinterpret_cast<const float4*>(A + i);
        *reinterpret_cast<__nv_bfloat162*>(&g_att[i  ]) = __floats2bfloat162_rn(v.x, v.y);
        *reinterpret_cast<__nv_bfloat162*>(&g_att[i+2]) = __floats2bfloat162_rn(v.z, v.w);
    }
}

// ---------------- kernel 1: c[b,e] = h@Wh^T + x@Wx^T + (bh+bx+ba) ----------------
// Block = 16 b x 32 e (grid 8 x 32). h/x tiles in 128 KB dynamic smem.
__global__ __launch_bounds__(256) void k_cvec2(
        const float* __restrict__ h, const float* __restrict__ x,
        const float* __restrict__ Wh, const float* __restrict__ Wx,
        const float* __restrict__ bh, const float* __restrict__ bx,
        const float* __restrict__ ba){
    extern __shared__ float sh[];          // hs[16*1024] xs[16*1024]
    float* hs = sh;
    float* xs = sh + 16*1024;
    const int tid = threadIdx.x, wid = tid>>5, lane = tid&31;
    const int b0 = blockIdx.x * 16;
    const int e0 = blockIdx.y * 32 + wid * 4;

    for (int i = tid; i < 4096; i += 256){
        int row = i >> 8, c = (i & 255) << 2;
        *reinterpret_cast<float4*>(&hs[row*1024 + c]) =
            *reinterpret_cast<const float4*>(h + (size_t)(b0+row)*1024 + c);
        *reinterpret_cast<float4*>(&xs[row*1024 + c]) =
            *reinterpret_cast<const float4*>(x + (size_t)(b0+row)*1024 + c);
    }
    __syncthreads();

    float acc[4][16];
    #pragma unroll
    for (int e = 0; e < 4; ++e)
        #pragma unroll
        for (int b = 0; b < 16; ++b) acc[e][b] = 0.f;

    const float4* wh4[4]; const float4* wx4[4];
    #pragma unroll
    for (int e = 0; e < 4; ++e){
        wh4[e] = reinterpret_cast<const float4*>(Wh + (size_t)(e0+e)*1024);
        wx4[e] = reinterpret_cast<const float4*>(Wx + (size_t)(e0+e)*1024);
    }

    #pragma unroll
    for (int k = 0; k < 8; ++k){
        const int d4 = lane*8 + k;
        float4 wv[4], xv[4];
        #pragma unroll
        for (int e = 0; e < 4; ++e){ wv[e] = wh4[e][d4]; xv[e] = wx4[e][d4]; }
        #pragma unroll
        for (int b = 0; b < 16; ++b){
            float4 hv = *reinterpret_cast<const float4*>(&hs[b*1024 + (d4<<2)]);
            float4 gv = *reinterpret_cast<const float4*>(&xs[b*1024 + (d4<<2)]);
            #pragma unroll
            for (int e = 0; e < 4; ++e){
                acc[e][b] += wv[e].x*hv.x + wv[e].y*hv.y + wv[e].z*hv.z + wv[e].w*hv.w;
                acc[e][b] += xv[e].x*gv.x + xv[e].y*gv.y + xv[e].z*gv.z + xv[e].w*gv.w;
            }
        }
    }

    #pragma unroll
    for (int e = 0; e < 4; ++e)
        #pragma unroll
        for (int b = 0; b < 16; ++b){
            float v = acc[e][b];
            v += __shfl_xor_sync(0xffffffffu, v, 16);
            v += __shfl_xor_sync(0xffffffffu, v, 8);
            v += __shfl_xor_sync(0xffffffffu, v, 4);
            v += __shfl_xor_sync(0xffffffffu, v, 2);
            v += __shfl_xor_sync(0xffffffffu, v, 1);
            acc[e][b] = v;
        }
    #pragma unroll
    for (int t = 0; t < 2; ++t){
        const int idx = lane + t*32;
        const int e = idx >> 4, b = idx & 15;
        const int eg = e0 + e;
        g_c[(size_t)(b0+b)*1024 + eg] = acc[e][b] + bh[eg] + bx[eg] + ba[eg];
    }
}

// ---------------- kernel 2: fused GEMM + tanh + dot(W_d2d) -> scores ----------------
// R9 structure; single change: B fragments via ldsm_x4 (n16 x k16), 6 LDSM per 16 MMA.
#define ABUF    8192               // 64 rows * 128B
#define B_OFF   16384
#define BBUF    32768              // 256 rows * 128B
#define CS_OFF  81920
#define WD_OFF  90112
#define SSC_OFF 94208
#define SM_SZ   94464

__global__ void __launch_bounds__(256, 2) k_scores(const float* __restrict__ wdd){
    extern __shared__ char sm[];
    const int tid = threadIdx.x, lane = tid & 31, wid = tid >> 5;
    const int m0 = blockIdx.x * 64;
    const int b0 = m0 / L_;
    const unsigned smb = smem_u32(sm);
    float* cs  = reinterpret_cast<float*>(sm + CS_OFF);
    float* wds = reinterpret_cast<float*>(sm + WD_OFF);
    float* ssc = reinterpret_cast<float*>(sm + SSC_OFF);

    // ---- constants ----
    {
        int b1 = (m0 + 63) / L_; if (b1 > B_-1) b1 = B_-1;
        for (int i = tid; i < 2048; i += 256){
            int w = i >> 10, e = i & 1023;
            cs[i] = g_c[(size_t)(w ? b1 : b0)*1024 + e];
        }
        for (int i = tid; i < 1024; i += 256) wds[i] = wdd[i];
        if (tid < 64) ssc[tid] = 0.f;
    }

    const int m_off = (wid >> 2) * 32;        // 0,32
    const int n_off = (wid & 3) * 64;         // 0..192 within 256-wide n-chunk
    const unsigned v  = (unsigned)(lane & 7); // swizzle key (row&7 for both operands)
    const unsigned ua = (unsigned)(lane >> 4);
    const unsigned ub = (unsigned)((lane >> 3) & 1);
    const unsigned a_row = smb + (unsigned)((m_off + (lane & 15)) * 128);
    unsigned b_row4[4];
    #pragma unroll
    for (int p = 0; p < 4; ++p)
        b_row4[p] = smb + B_OFF + (unsigned)((n_off + p*16 + (lane & 7)
                  + ((lane >> 4) << 3)) * 128);

    const float* crow[2][2]; int rowl[2][2];
    #pragma unroll
    for (int mt = 0; mt < 2; ++mt)
        #pragma unroll
        for (int hf = 0; hf < 2; ++hf){
            const int r = m_off + mt*16 + (lane >> 2) + hf*8;
            rowl[mt][hf] = r;
            crow[mt][hf] = cs + (((m0 + r)/L_ != b0) ? 1024 : 0);
        }

    // tile loader (R9 form): step t -> n0=(t>>4)*256, kk=(t&15)*64
    auto load_step = [&](int t, int buf){
        const int n0 = (t >> 4) * 256, kk = (t & 15) * 64;
        #pragma unroll
        for (int i = 0; i < 2; ++i){             // A: 64x64 bf16
            const int idx = tid + i*256;
            const int r = idx >> 3, c = idx & 7;
            cp16(smb + (unsigned)(buf*ABUF + r*128 + (((unsigned)c ^ (r&7))<<4)),
                 g_att + ((size_t)(m0 + r) << 10) + kk + c*8);
        }
        #pragma unroll
        for (int i = 0; i < 8; ++i){             // B: 256x64 bf16
            const int idx = tid + i*256;
            const int r = idx >> 3, c = idx & 7;
            cp16(smb + B_OFF + (unsigned)(buf*BBUF + r*128 + (((unsigned)c ^ (r&7))<<4)),
                 g_wa + ((size_t)(n0 + r) << 10) + kk + c*8);
        }
    };

    float acc[2][8][4];
    load_step(0, 0);
    cp_commit();

    for (int s = 0; s < 64; ++s){
        const int kc = s & 15;
        cp_wait0();                  // step-s tiles arrived
        __syncthreads();             // all warps done reading buffer (s+1)&1
        if (s < 63){ load_step(s+1, (s+1)&1); cp_commit(); }

        if (kc == 0){
            #pragma unroll
            for (int mt = 0; mt < 2; ++mt)
                #pragma unroll
                for (int nt = 0; nt < 8; ++nt)
                    #pragma unroll
                    for (int i = 0; i < 4; ++i) acc[mt][nt][i] = 0.f;
        }
        const unsigned ao = (unsigned)((s & 1) * ABUF);
        const unsigned bo = (unsigned)((s & 1) * BBUF);
        #pragma unroll
        for (int ks = 0; ks < 4; ++ks){
            unsigned af[2][4], bf[4][4];
            const unsigned ca = (((unsigned)(2*ks) + ua) ^ v) << 4;
            #pragma unroll
            for (int mt = 0; mt < 2; ++mt)
                ldsm_x4(af[mt], a_row + ao + (unsigned)(mt*2048) + ca);
            const unsigned cb = (((unsigned)(2*ks) + ub) ^ v) << 4;
            #pragma unroll
            for (int p = 0; p < 4; ++p)
                ldsm_x4(bf[p], b_row4[p] + bo + cb);
            #pragma unroll
            for (int mt = 0; mt < 2; ++mt)
                #pragma unroll
                for (int p = 0; p < 4; ++p){
                    mma16816(acc[mt][2*p  ], af[mt], bf[p][0], bf[p][1]);
                    mma16816(acc[mt][2*p+1], af[mt], bf[p][2], bf[p][3]);
                }
        }

        if (kc == 15){   // n-chunk complete: fused tanh*W_d2d epilogue
            const int n0c = (s >> 4) * 256;
            #pragma unroll
            for (int mt = 0; mt < 2; ++mt)
                #pragma unroll
                for (int hf = 0; hf < 2; ++hf){
                    float vsum = 0.f;
                    const float* cr = crow[mt][hf];
                    #pragma unroll
                    for (int nt = 0; nt < 8; ++nt){
                        const int e0 = n0c + n_off + nt*8 + (lane & 3)*2;
                        vsum += tanh_fast(acc[mt][nt][hf*2+0] + cr[e0  ]) * wds[e0  ];
                        vsum += tanh_fast(acc[mt][nt][hf*2+1] + cr[e0+1]) * wds[e0+1];
                    }
                    vsum += __shfl_xor_sync(0xffffffffu, vsum, 1);
                    vsum += __shfl_xor_sync(0xffffffffu, vsum, 2);
                    if ((lane & 3) == 0) atomicAdd(&ssc[rowl[mt][hf]], vsum);
                }
        }
    }
    __syncthreads();
    if (tid < 64) g_scores[m0 + tid] = ssc[tid];   // b_d2d dropped (softmax shift-invariant)
}

// ---------------- kernel 3a: softmax + L-split(7) weighted partial sums ----------------
__global__ __launch_bounds__(256) void k_outp(const float* __restrict__ att){
    __shared__ float sc[256];
    __shared__ float red[256];
    const int b = blockIdx.x, q = blockIdx.y, tid = threadIdx.x;
    const float s = (tid < L_) ? g_scores[b*L_ + tid] : -1e30f;
    red[tid] = s; __syncthreads();
    #pragma unroll
    for (int o = 128; o > 0; o >>= 1){
        if (tid < o) red[tid] = fmaxf(red[tid], red[tid+o]);
        __syncthreads();
    }
    const float mx = red[0]; __syncthreads();
    const float e = (tid < L_) ? __expf(s - mx) : 0.f;
    sc[tid] = e; red[tid] = e; __syncthreads();
    #pragma unroll
    for (int o = 128; o > 0; o >>= 1){
        if (tid < o) red[tid] += red[tid+o];
        __syncthreads();
    }
    const float inv = 1.f / red[0];
    __syncthreads();

    const float4* ap = reinterpret_cast<const float4*>(att)
                     + (size_t)b*L_*256 + (size_t)q*28*256 + tid;
    float4 acc = make_float4(0.f,0.f,0.f,0.f);
    #pragma unroll 7
    for (int l = 0; l < 28; ++l){
        float4 vv = ap[(size_t)l*256];
        const float wl = sc[q*28 + l] * inv;
        acc.x += wl*vv.x; acc.y += wl*vv.y; acc.z += wl*vv.z; acc.w += wl*vv.w;
    }
    reinterpret_cast<float4*>(g_part)[((size_t)q*B_ + b)*256 + tid] = acc;
}

// ---------------- kernel 3b: combine 7 partials ----------------
__global__ __launch_bounds__(256) void k_out2(float* __restrict__ out){
    const int b = blockIdx.x, tid = threadIdx.x;
    const float4* p = reinterpret_cast<const float4*>(g_part);
    float4 r = make_float4(0.f,0.f,0.f,0.f);
    #pragma unroll
    for (int q = 0; q < 7; ++q){
        float4 a = p[((size_t)q*B_ + b)*256 + tid];
        r.x += a.x; r.y += a.y; r.z += a.z; r.w += a.w;
    }
    reinterpret_cast<float4*>(out)[(size_t)b*256 + tid] = r;
}

// ---------------- launch ----------------
extern "C" void kernel_launch(void* const* d_in, const int* in_sizes, int n_in,
                              void* d_out, int out_size) {
    const float* x   = (const float*)d_in[0];
    const float* att = (const float*)d_in[1];
    const float* h   = (const float*)d_in[2];
    const float* Wa  = (const float*)d_in[3];
    const float* ba  = (const float*)d_in[4];
    const float* Wh  = (const float*)d_in[5];
    const float* bh  = (const float*)d_in[6];
    const float* Wx  = (const float*)d_in[7];
    const float* bx  = (const float*)d_in[8];
    const float* wd  = (const float*)d_in[9];
    float* out = (float*)d_out;

    cudaFuncSetAttribute(k_scores, cudaFuncAttributeMaxDynamicSharedMemorySize, SM_SZ);
    cudaFuncSetAttribute(k_cvec2, cudaFuncAttributeMaxDynamicSharedMemorySize, 131072);

    k_convert<<<1024 + 25088, 256>>>(Wa, att);
    k_cvec2<<<dim3(8, 32), 256, 131072>>>(h, x, Wh, Wx, bh, bx, ba);
    k_scores<<<M_/64, 256, SM_SZ>>>(wd);
    k_outp<<<dim3(B_, 7), 256>>>(att);
    k_out2<<<B_, 256>>>(out);
}

// round 13
// speedup vs baseline: 1.4356x; 1.0248x over previous
#include <cuda_runtime.h>
#include <cuda_bf16.h>
#include <cstdint>

#define B_  128
#define L_  196
#define D_  1024
#define M_  (B_*L_)            // 25088

// ---------------- scratch (device globals; no allocation) ----------------
__device__ float g_c[B_*D_];          // c[b,e] = att_h + att_x + 3 biases
__device__ float g_scores[M_];        // pre-softmax scores
__device__ float g_part[7*B_*D_];     // L-split partial outputs
__device__ __nv_bfloat16 g_wa[D_*D_]; // W_a2a bf16
__device__ __nv_bfloat16 g_att[(size_t)M_*D_]; // att bf16 (51.4 MB)

// ---------------- helpers ----------------
static __device__ __forceinline__ float tanh_fast(float x){
    float y; asm("tanh.approx.f32 %0, %1;" : "=f"(y) : "f"(x)); return y;
}
static __device__ __forceinline__ unsigned smem_u32(const void* p){
    return (unsigned)__cvta_generic_to_shared(p);
}
static __device__ __forceinline__ void ldsm_x4(unsigned r[4], unsigned a){
    asm volatile("ldmatrix.sync.aligned.m8n8.x4.shared.b16 {%0,%1,%2,%3}, [%4];"
        : "=r"(r[0]),"=r"(r[1]),"=r"(r[2]),"=r"(r[3]) : "r"(a));
}
static __device__ __forceinline__ void mma16816(float d[4], const unsigned a[4],
                                                unsigned b0, unsigned b1){
    asm volatile("mma.sync.aligned.m16n8k16.row.col.f32.bf16.bf16.f32 "
        "{%0,%1,%2,%3}, {%4,%5,%6,%7}, {%8,%9}, {%0,%1,%2,%3};"
        : "+f"(d[0]),"+f"(d[1]),"+f"(d[2]),"+f"(d[3])
        : "r"(a[0]),"r"(a[1]),"r"(a[2]),"r"(a[3]),"r"(b0),"r"(b1));
}
static __device__ __forceinline__ void cp16(unsigned dst, const void* src){
    asm volatile("cp.async.cg.shared.global [%0], [%1], 16;" :: "r"(dst), "l"(src));
}
static __device__ __forceinline__ void cp_commit(){ asm volatile("cp.async.commit_group;"); }
static __device__ __forceinline__ void cp_wait0(){
    asm volatile("cp.async.wait_group 0;" ::: "memory");
}
static __device__ __forceinline__ unsigned pack_bf2(float a, float b){
    __nv_bfloat162 p = __floats2bfloat162_rn(a, b);
    return *reinterpret_cast<unsigned*>(&p);
}

// ---------------- kernel 0: cvec (blocks 0..255) + W convert (blocks 256..1279) ----
// cvec: block = 16 b x 32 e; h/x tiles in 128 KB dynamic smem.
__global__ __launch_bounds__(256) void k_prep2(
        const float* __restrict__ W,
        const float* __restrict__ h, const float* __restrict__ x,
        const float* __restrict__ Wh, const float* __restrict__ Wx,
        const float* __restrict__ bh, const float* __restrict__ bx,
        const float* __restrict__ ba){
    extern __shared__ float sh[];          // hs[16*1024] xs[16*1024]
    const int bid = blockIdx.x, tid = threadIdx.x;
    if (bid >= 256){                       // ---- W_a2a fp32 -> bf16 ----
        int i = ((bid-256)*256 + tid)*4;
        float4 v = *reinterpret_cast<const float4*>(W + i);
        *reinterpret_cast<__nv_bfloat162*>(&g_wa[i  ]) = __floats2bfloat162_rn(v.x, v.y);
        *reinterpret_cast<__nv_bfloat162*>(&g_wa[i+2]) = __floats2bfloat162_rn(v.z, v.w);
        return;
    }
    // ---- cvec ----
    float* hs = sh;
    float* xs = sh + 16*1024;
    const int wid = tid>>5, lane = tid&31;
    const int b0 = (bid & 7) * 16;
    const int e0 = (bid >> 3) * 32 + wid * 4;

    for (int i = tid; i < 4096; i += 256){
        int row = i >> 8, c = (i & 255) << 2;
        *reinterpret_cast<float4*>(&hs[row*1024 + c]) =
            *reinterpret_cast<const float4*>(h + (size_t)(b0+row)*1024 + c);
        *reinterpret_cast<float4*>(&xs[row*1024 + c]) =
            *reinterpret_cast<const float4*>(x + (size_t)(b0+row)*1024 + c);
    }
    __syncthreads();

    float acc[4][16];
    #pragma unroll
    for (int e = 0; e < 4; ++e)
        #pragma unroll
        for (int b = 0; b < 16; ++b) acc[e][b] = 0.f;

    const float4* wh4[4]; const float4* wx4[4];
    #pragma unroll
    for (int e = 0; e < 4; ++e){
        wh4[e] = reinterpret_cast<const float4*>(Wh + (size_t)(e0+e)*1024);
        wx4[e] = reinterpret_cast<const float4*>(Wx + (size_t)(e0+e)*1024);
    }

    #pragma unroll
    for (int k = 0; k < 8; ++k){
        const int d4 = lane*8 + k;
        float4 wv[4], xv[4];
        #pragma unroll
        for (int e = 0; e < 4; ++e){ wv[e] = wh4[e][d4]; xv[e] = wx4[e][d4]; }
        #pragma unroll
        for (int b = 0; b < 16; ++b){
            float4 hv = *reinterpret_cast<const float4*>(&hs[b*1024 + (d4<<2)]);
            float4 gv = *reinterpret_cast<const float4*>(&xs[b*1024 + (d4<<2)]);
            #pragma unroll
            for (int e = 0; e < 4; ++e){
                acc[e][b] += wv[e].x*hv.x + wv[e].y*hv.y + wv[e].z*hv.z + wv[e].w*hv.w;
                acc[e][b] += xv[e].x*gv.x + xv[e].y*gv.y + xv[e].z*gv.z + xv[e].w*gv.w;
            }
        }
    }

    #pragma unroll
    for (int e = 0; e < 4; ++e)
        #pragma unroll
        for (int b = 0; b < 16; ++b){
            float v = acc[e][b];
            v += __shfl_xor_sync(0xffffffffu, v, 16);
            v += __shfl_xor_sync(0xffffffffu, v, 8);
            v += __shfl_xor_sync(0xffffffffu, v, 4);
            v += __shfl_xor_sync(0xffffffffu, v, 2);
            v += __shfl_xor_sync(0xffffffffu, v, 1);
            acc[e][b] = v;
        }
    #pragma unroll
    for (int t = 0; t < 2; ++t){
        const int idx = lane + t*32;
        const int e = idx >> 4, b = idx & 15;
        const int eg = e0 + e;
        g_c[(size_t)(b0+b)*1024 + eg] = acc[e][b] + bh[eg] + bx[eg] + ba[eg];
    }
}

// ---------------- kernel 1: fused GEMM + tanh + dot(W_d2d) -> scores ----------------
// R12 mainloop unchanged; prologue self-converts this CTA's 64 att rows to g_att.
#define ABUF    8192               // 64 rows * 128B
#define B_OFF   16384
#define BBUF    32768              // 256 rows * 128B
#define CS_OFF  81920
#define WD_OFF  90112
#define SSC_OFF 94208
#define SM_SZ   94464

__global__ void __launch_bounds__(256, 2) k_scores(const float* __restrict__ att,
                                                   const float* __restrict__ wdd){
    extern __shared__ char sm[];
    const int tid = threadIdx.x, lane = tid & 31, wid = tid >> 5;
    const int m0 = blockIdx.x * 64;
    const int b0 = m0 / L_;
    const unsigned smb = smem_u32(sm);
    float* cs  = reinterpret_cast<float*>(sm + CS_OFF);
    float* wds = reinterpret_cast<float*>(sm + WD_OFF);
    float* ssc = reinterpret_cast<float*>(sm + SSC_OFF);

    // ---- constants ----
    {
        int b1 = (m0 + 63) / L_; if (b1 > B_-1) b1 = B_-1;
        for (int i = tid; i < 2048; i += 256){
            int w = i >> 10, e = i & 1023;
            cs[i] = g_c[(size_t)(w ? b1 : b0)*1024 + e];
        }
        for (int i = tid; i < 1024; i += 256) wds[i] = wdd[i];
        if (tid < 64) ssc[tid] = 0.f;
    }

    // ---- self-convert this CTA's att rows fp32 -> bf16 into g_att ----
    {
        const float4* asrc = reinterpret_cast<const float4*>(att + (size_t)m0*1024);
        uint4* adst = reinterpret_cast<uint4*>(g_att + (size_t)m0*1024);
        #pragma unroll 8
        for (int g = tid; g < 8192; g += 256){
            float4 v0 = asrc[2*g], v1 = asrc[2*g+1];
            uint4 o;
            o.x = pack_bf2(v0.x, v0.y); o.y = pack_bf2(v0.z, v0.w);
            o.z = pack_bf2(v1.x, v1.y); o.w = pack_bf2(v1.z, v1.w);
            adst[g] = o;
        }
    }
    __syncthreads();   // converted rows visible (L2) before cp.async reads them

    const int m_off = (wid >> 2) * 32;        // 0,32
    const int n_off = (wid & 3) * 64;         // 0..192 within 256-wide n-chunk
    const unsigned v  = (unsigned)(lane & 7); // swizzle key
    const unsigned ua = (unsigned)(lane >> 4);
    const unsigned ub = (unsigned)((lane >> 3) & 1);
    const unsigned a_row = smb + (unsigned)((m_off + (lane & 15)) * 128);
    unsigned b_row4[4];
    #pragma unroll
    for (int p = 0; p < 4; ++p)
        b_row4[p] = smb + B_OFF + (unsigned)((n_off + p*16 + (lane & 7)
                  + ((lane >> 4) << 3)) * 128);

    const float* crow[2][2]; int rowl[2][2];
    #pragma unroll
    for (int mt = 0; mt < 2; ++mt)
        #pragma unroll
        for (int hf = 0; hf < 2; ++hf){
            const int r = m_off + mt*16 + (lane >> 2) + hf*8;
            rowl[mt][hf] = r;
            crow[mt][hf] = cs + (((m0 + r)/L_ != b0) ? 1024 : 0);
        }

    auto load_step = [&](int t, int buf){
        const int n0 = (t >> 4) * 256, kk = (t & 15) * 64;
        #pragma unroll
        for (int i = 0; i < 2; ++i){             // A: 64x64 bf16
            const int idx = tid + i*256;
            const int r = idx >> 3, c = idx & 7;
            cp16(smb + (unsigned)(buf*ABUF + r*128 + (((unsigned)c ^ (r&7))<<4)),
                 g_att + ((size_t)(m0 + r) << 10) + kk + c*8);
        }
        #pragma unroll
        for (int i = 0; i < 8; ++i){             // B: 256x64 bf16
            const int idx = tid + i*256;
            const int r = idx >> 3, c = idx & 7;
            cp16(smb + B_OFF + (unsigned)(buf*BBUF + r*128 + (((unsigned)c ^ (r&7))<<4)),
                 g_wa + ((size_t)(n0 + r) << 10) + kk + c*8);
        }
    };

    float acc[2][8][4];
    load_step(0, 0);
    cp_commit();

    for (int s = 0; s < 64; ++s){
        const int kc = s & 15;
        cp_wait0();                  // step-s tiles arrived
        __syncthreads();             // all warps done reading buffer (s+1)&1
        if (s < 63){ load_step(s+1, (s+1)&1); cp_commit(); }

        if (kc == 0){
            #pragma unroll
            for (int mt = 0; mt < 2; ++mt)
                #pragma unroll
                for (int nt = 0; nt < 8; ++nt)
                    #pragma unroll
                    for (int i = 0; i < 4; ++i) acc[mt][nt][i] = 0.f;
        }
        const unsigned ao = (unsigned)((s & 1) * ABUF);
        const unsigned bo = (unsigned)((s & 1) * BBUF);
        #pragma unroll
        for (int ks = 0; ks < 4; ++ks){
            unsigned af[2][4], bf[4][4];
            const unsigned ca = (((unsigned)(2*ks) + ua) ^ v) << 4;
            #pragma unroll
            for (int mt = 0; mt < 2; ++mt)
                ldsm_x4(af[mt], a_row + ao + (unsigned)(mt*2048) + ca);
            const unsigned cb = (((unsigned)(2*ks) + ub) ^ v) << 4;
            #pragma unroll
            for (int p = 0; p < 4; ++p)
                ldsm_x4(bf[p], b_row4[p] + bo + cb);
            #pragma unroll
            for (int mt = 0; mt < 2; ++mt)
                #pragma unroll
                for (int p = 0; p < 4; ++p){
                    mma16816(acc[mt][2*p  ], af[mt], bf[p][0], bf[p][1]);
                    mma16816(acc[mt][2*p+1], af[mt], bf[p][2], bf[p][3]);
                }
        }

        if (kc == 15){   // n-chunk complete: fused tanh*W_d2d epilogue
            const int n0c = (s >> 4) * 256;
            #pragma unroll
            for (int mt = 0; mt < 2; ++mt)
                #pragma unroll
                for (int hf = 0; hf < 2; ++hf){
                    float vsum = 0.f;
                    const float* cr = crow[mt][hf];
                    #pragma unroll
                    for (int nt = 0; nt < 8; ++nt){
                        const int e0 = n0c + n_off + nt*8 + (lane & 3)*2;
                        vsum += tanh_fast(acc[mt][nt][hf*2+0] + cr[e0  ]) * wds[e0  ];
                        vsum += tanh_fast(acc[mt][nt][hf*2+1] + cr[e0+1]) * wds[e0+1];
                    }
                    vsum += __shfl_xor_sync(0xffffffffu, vsum, 1);
                    vsum += __shfl_xor_sync(0xffffffffu, vsum, 2);
                    if ((lane & 3) == 0) atomicAdd(&ssc[rowl[mt][hf]], vsum);
                }
        }
    }
    __syncthreads();
    if (tid < 64) g_scores[m0 + tid] = ssc[tid];   // b_d2d dropped (softmax shift-invariant)
}

// ---------------- kernel 2: softmax + L-split(7) weighted partial sums ----------------
__global__ __launch_bounds__(256) void k_outp(const float* __restrict__ att){
    __shared__ float sc[256];
    __shared__ float red[256];
    const int b = blockIdx.x, q = blockIdx.y, tid = threadIdx.x;
    const float s = (tid < L_) ? g_scores[b*L_ + tid] : -1e30f;
    red[tid] = s; __syncthreads();
    #pragma unroll
    for (int o = 128; o > 0; o >>= 1){
        if (tid < o) red[tid] = fmaxf(red[tid], red[tid+o]);
        __syncthreads();
    }
    const float mx = red[0]; __syncthreads();
    const float e = (tid < L_) ? __expf(s - mx) : 0.f;
    sc[tid] = e; red[tid] = e; __syncthreads();
    #pragma unroll
    for (int o = 128; o > 0; o >>= 1){
        if (tid < o) red[tid] += red[tid+o];
        __syncthreads();
    }
    const float inv = 1.f / red[0];
    __syncthreads();

    const float4* ap = reinterpret_cast<const float4*>(att)
                     + (size_t)b*L_*256 + (size_t)q*28*256 + tid;
    float4 acc = make_float4(0.f,0.f,0.f,0.f);
    #pragma unroll 7
    for (int l = 0; l < 28; ++l){
        float4 vv = ap[(size_t)l*256];
        const float wl = sc[q*28 + l] * inv;
        acc.x += wl*vv.x; acc.y += wl*vv.y; acc.z += wl*vv.z; acc.w += wl*vv.w;
    }
    reinterpret_cast<float4*>(g_part)[((size_t)q*B_ + b)*256 + tid] = acc;
}

// ---------------- kernel 3: combine 7 partials ----------------
__global__ __launch_bounds__(256) void k_out2(float* __restrict__ out){
    const int b = blockIdx.x, tid = threadIdx.x;
    const float4* p = reinterpret_cast<const float4*>(g_part);
    float4 r = make_float4(0.f,0.f,0.f,0.f);
    #pragma unroll
    for (int q = 0; q < 7; ++q){
        float4 a = p[((size_t)q*B_ + b)*256 + tid];
        r.x += a.x; r.y += a.y; r.z += a.z; r.w += a.w;
    }
    reinterpret_cast<float4*>(out)[(size_t)b*256 + tid] = r;
}

// ---------------- launch ----------------
extern "C" void kernel_launch(void* const* d_in, const int* in_sizes, int n_in,
                              void* d_out, int out_size) {
    const float* x   = (const float*)d_in[0];
    const float* att = (const float*)d_in[1];
    const float* h   = (const float*)d_in[2];
    const float* Wa  = (const float*)d_in[3];
    const float* ba  = (const float*)d_in[4];
    const float* Wh  = (const float*)d_in[5];
    const float* bh  = (const float*)d_in[6];
    const float* Wx  = (const float*)d_in[7];
    const float* bx  = (const float*)d_in[8];
    const float* wd  = (const float*)d_in[9];
    float* out = (float*)d_out;

    cudaFuncSetAttribute(k_scores, cudaFuncAttributeMaxDynamicSharedMemorySize, SM_SZ);
    cudaFuncSetAttribute(k_prep2, cudaFuncAttributeMaxDynamicSharedMemorySize, 131072);

    k_prep2<<<256 + 1024, 256, 131072>>>(Wa, h, x, Wh, Wx, bh, bx, ba);
    k_scores<<<M_/64, 256, SM_SZ>>>(att, wd);
    k_outp<<<dim3(B_, 7), 256>>>(att);
    k_out2<<<B_, 256>>>(out);
}